// round 6
// baseline (speedup 1.0000x reference)
#include <cuda_runtime.h>
#include <math.h>

// ---------------------------------------------------------------------------
// PADigitalTwin, 2-launch structure with f32x2 packed math.
//  pa_main: Volterra (packed FFMA2) + fused phase rotation -> out,
//           per-block power partials (pre-rotation power; magnitude-invariant).
//  pa_epi : per-block deterministic reduce of partials -> ns, then
//           out += ns * awgn   (out is L2-resident from pa_main).
//
//   x [16,131072,2]  cr/ci [4,5]  awgn [16,131068,2]  pn [16,131068]
//   out [16,131068,2]   (all f32)
// ---------------------------------------------------------------------------

#define MEMD      5
#define SLEN      131072
#define OUTLEN    131068          // SLEN - MEMD + 1
#define BATCH     16
#define JOBS_PB   (OUTLEN / 4)    // 32767 (4 outputs per job)
#define BLOCK     256
#define GRIDX     ((JOBS_PB + BLOCK - 1) / BLOCK)   // 128
#define NPART     (GRIDX * BATCH)                   // 2048

#define EN4       ((size_t)BATCH * OUTLEN * 2 / 4)  // 1,048,544 float4
#define EGRID     2048                              // 512 float4 per block

typedef unsigned long long u64;

__device__ float g_partials[NPART];

// ---- f32x2 helpers (FFMA2 path: PTX-only on sm_103a) -----------------------
__device__ __forceinline__ u64 pk2(float lo, float hi) {
    u64 r; asm("mov.b64 %0, {%1, %2};" : "=l"(r) : "f"(lo), "f"(hi)); return r;
}
__device__ __forceinline__ void upk2(u64 v, float& lo, float& hi) {
    asm("mov.b64 {%0, %1}, %2;" : "=f"(lo), "=f"(hi) : "l"(v));
}
__device__ __forceinline__ u64 fma2_(u64 a, u64 b, u64 c) {
    u64 d;
    asm("fma.rn.f32x2 %0, %1, %2, %3;" : "=l"(d) : "l"(a), "l"(b), "l"(c));
    return d;
}

// ---------------- Pass 1: Volterra + rotation -> out ------------------------
__global__ __launch_bounds__(BLOCK)
void pa_main(const float* __restrict__ x,
             const float* __restrict__ crg,
             const float* __restrict__ cig,
             const float* __restrict__ pn,
             float* __restrict__ out)
{
    // duplicated packed coeffs: scr2[m][k] = (cr[k][m], cr[k][m])
    __shared__ u64 scr2[MEMD][4], sci2[MEMD][4];
    if (threadIdx.x < 40) {
        const int t = threadIdx.x;
        if (t < 20) {
            float v = __ldg(&crg[t]);            // t = k*5+m
            scr2[t % 5][t / 5] = pk2(v, v);
        } else {
            const int u = t - 20;
            float v = __ldg(&cig[u]);
            sci2[u % 5][u / 5] = pk2(v, v);
        }
    }
    __syncthreads();

    const int j = blockIdx.x * BLOCK + threadIdx.x;
    const int b = blockIdx.y;
    float acc = 0.f;

    if (j < JOBS_PB) {
        const float4* xb4 = (const float4*)(x + (size_t)b * SLEN * 2);
        float I[8], Q[8], a2[8];
#pragma unroll
        for (int v = 0; v < 4; v++) {
            float4 p = __ldg(&xb4[j * 2 + v]);   // samples 4j+2v, 4j+2v+1
            I[2 * v]     = p.x;  Q[2 * v]     = p.y;
            I[2 * v + 1] = p.z;  Q[2 * v + 1] = p.w;
        }
#pragma unroll
        for (int s = 0; s < 8; s++)
            a2[s] = fmaf(I[s], I[s], Q[s] * Q[s]);

        // packed adjacent-sample pairs (t, t+1)
        u64 ii[7], qq[7], mq[7], aa[7];
#pragma unroll
        for (int t = 0; t < 7; t++) {
            ii[t] = pk2(I[t], I[t + 1]);
            qq[t] = pk2(Q[t], Q[t + 1]);
            mq[t] = pk2(-Q[t], -Q[t + 1]);
            aa[t] = pk2(a2[t], a2[t + 1]);
        }

        // packed accumulators: lanes = output pair (0,1) and (2,3)
        u64 sr0 = 0, si0 = 0, sr1 = 0, si1 = 0;
#pragma unroll
        for (int m = 0; m < MEMD; m++) {
            const int t0 = 4 - m;                // windows for outputs (0,1)
            const int t1 = 6 - m;                // windows for outputs (2,3)
            u64 fr0 = fma2_(scr2[m][3], aa[t0], scr2[m][2]);
            fr0     = fma2_(fr0,        aa[t0], scr2[m][1]);
            fr0     = fma2_(fr0,        aa[t0], scr2[m][0]);
            u64 fi0 = fma2_(sci2[m][3], aa[t0], sci2[m][2]);
            fi0     = fma2_(fi0,        aa[t0], sci2[m][1]);
            fi0     = fma2_(fi0,        aa[t0], sci2[m][0]);
            sr0 = fma2_(fr0, ii[t0], sr0);
            sr0 = fma2_(fi0, mq[t0], sr0);
            si0 = fma2_(fr0, qq[t0], si0);
            si0 = fma2_(fi0, ii[t0], si0);

            u64 fr1 = fma2_(scr2[m][3], aa[t1], scr2[m][2]);
            fr1     = fma2_(fr1,        aa[t1], scr2[m][1]);
            fr1     = fma2_(fr1,        aa[t1], scr2[m][0]);
            u64 fi1 = fma2_(sci2[m][3], aa[t1], sci2[m][2]);
            fi1     = fma2_(fi1,        aa[t1], sci2[m][1]);
            fi1     = fma2_(fi1,        aa[t1], sci2[m][0]);
            sr1 = fma2_(fr1, ii[t1], sr1);
            sr1 = fma2_(fi1, mq[t1], sr1);
            si1 = fma2_(fr1, qq[t1], si1);
            si1 = fma2_(fi1, ii[t1], si1);
        }

        float yr[4], yi[4];
        upk2(sr0, yr[0], yr[1]);  upk2(si0, yi[0], yi[1]);
        upk2(sr1, yr[2], yr[3]);  upk2(si1, yi[2], yi[3]);

#pragma unroll
        for (int o = 0; o < 4; o++)
            acc = fmaf(yr[o], yr[o], fmaf(yi[o], yi[o], acc));

        // fused phase rotation (magnitude-preserving; power already taken)
        const float4* pn4 = (const float4*)(pn + (size_t)b * OUTLEN);
        float4 p = __ldg(&pn4[j]);
        const float KRAD = 0.008726646259971648f;    // 0.5*pi/180
        float pr[4] = {p.x, p.y, p.z, p.w};
        float ov[8];
#pragma unroll
        for (int o = 0; o < 4; o++) {
            float c, s;
            __sincosf(pr[o] * KRAD, &s, &c);
            ov[2 * o]     = yr[o] * c - yi[o] * s;
            ov[2 * o + 1] = yr[o] * s + yi[o] * c;
        }
        float4* out4 = (float4*)(out + (size_t)b * OUTLEN * 2);
        out4[j * 2]     = make_float4(ov[0], ov[1], ov[2], ov[3]);
        out4[j * 2 + 1] = make_float4(ov[4], ov[5], ov[6], ov[7]);
    }

    // deterministic block reduction -> partial
    __shared__ float shr[BLOCK / 32];
#pragma unroll
    for (int off = 16; off > 0; off >>= 1)
        acc += __shfl_down_sync(0xffffffffu, acc, off);
    if ((threadIdx.x & 31) == 0) shr[threadIdx.x >> 5] = acc;
    __syncthreads();
    if (threadIdx.x < BLOCK / 32) {
        float v = shr[threadIdx.x];
#pragma unroll
        for (int off = (BLOCK / 32) / 2; off > 0; off >>= 1)
            v += __shfl_down_sync(0xffu, v, off);
        if (threadIdx.x == 0)
            g_partials[blockIdx.y * GRIDX + blockIdx.x] = v;
    }
}

// ---------------- Pass 2: redundant reduce + out += ns*awgn -----------------
__global__ __launch_bounds__(BLOCK)
void pa_epi(const float* __restrict__ awgn,
            float* __restrict__ out)
{
    // every block computes ns identically (deterministic fixed-order sum)
    __shared__ double shd[BLOCK];
    double sd = 0.0;
#pragma unroll
    for (int i = 0; i < NPART / BLOCK; i++)
        sd += (double)g_partials[threadIdx.x + i * BLOCK];
    shd[threadIdx.x] = sd;
    __syncthreads();
#pragma unroll
    for (int off = BLOCK / 2; off > 0; off >>= 1) {
        if (threadIdx.x < off) shd[threadIdx.x] += shd[threadIdx.x + off];
        __syncthreads();
    }
    const double mean = shd[0] / ((double)BATCH * (double)OUTLEN);
    const float ns = (float)sqrt(mean * 0.5 * 1.0e-6);   // 10^(-60/10)

    const float4* aw4 = (const float4*)awgn;
    float4* o4 = (float4*)out;

    size_t i0 = (size_t)blockIdx.x * (2 * BLOCK) + threadIdx.x;
    if (i0 < EN4) {
        float4 a = __ldg(&aw4[i0]);
        float4 o = o4[i0];                         // L2 hit (just written)
        o.x = fmaf(a.x, ns, o.x);  o.y = fmaf(a.y, ns, o.y);
        o.z = fmaf(a.z, ns, o.z);  o.w = fmaf(a.w, ns, o.w);
        o4[i0] = o;
    }
    i0 += BLOCK;
    if (i0 < EN4) {
        float4 a = __ldg(&aw4[i0]);
        float4 o = o4[i0];
        o.x = fmaf(a.x, ns, o.x);  o.y = fmaf(a.y, ns, o.y);
        o.z = fmaf(a.z, ns, o.z);  o.w = fmaf(a.w, ns, o.w);
        o4[i0] = o;
    }
}

// ---------------------------------------------------------------------------
extern "C" void kernel_launch(void* const* d_in, const int* in_sizes, int n_in,
                              void* d_out, int out_size)
{
    const float* x    = (const float*)d_in[0];
    const float* cr   = (const float*)d_in[1];
    const float* ci   = (const float*)d_in[2];
    const float* awgn = (const float*)d_in[3];
    const float* pn   = (const float*)d_in[4];
    float* out        = (float*)d_out;

    pa_main<<<dim3(GRIDX, BATCH), BLOCK>>>(x, cr, ci, pn, out);
    pa_epi<<<EGRID, BLOCK>>>(awgn, out);
}

// round 7
// speedup vs baseline: 2.5508x; 2.5508x over previous
#include <cuda_runtime.h>
#include <math.h>

// ---------------------------------------------------------------------------
// PADigitalTwin, 3-launch structure with f32x2 packed math.
//  pa_main  : Volterra (packed FFMA2) + fused phase rotation -> out,
//             per-block power partials (pre-rotation; rotation is unitary).
//  pa_reduce: 1 block, partials -> g_noise_std.
//  pa_epi   : out += ns * awgn (out is L2-resident from pa_main).
//
//   x [16,131072,2]  cr/ci [4,5]  awgn [16,131068,2]  pn [16,131068]
//   out [16,131068,2]   (all f32)
// ---------------------------------------------------------------------------

#define MEMD      5
#define SLEN      131072
#define OUTLEN    131068          // SLEN - MEMD + 1
#define BATCH     16
#define JOBS_PB   (OUTLEN / 4)    // 32767 (4 outputs per job)
#define BLOCK     256
#define GRIDX     ((JOBS_PB + BLOCK - 1) / BLOCK)   // 128
#define NPART     (GRIDX * BATCH)                   // 2048

#define EN4       ((size_t)BATCH * OUTLEN * 2 / 4)  // 1,048,544 float4
#define EGRID     2048                              // 512 float4 per block

typedef unsigned long long u64;

__device__ float g_partials[NPART];
__device__ float g_noise_std;

// ---- f32x2 helpers (FFMA2 path: PTX-only on sm_103a) -----------------------
__device__ __forceinline__ u64 pk2(float lo, float hi) {
    u64 r; asm("mov.b64 %0, {%1, %2};" : "=l"(r) : "f"(lo), "f"(hi)); return r;
}
__device__ __forceinline__ void upk2(u64 v, float& lo, float& hi) {
    asm("mov.b64 {%0, %1}, %2;" : "=f"(lo), "=f"(hi) : "l"(v));
}
__device__ __forceinline__ u64 fma2_(u64 a, u64 b, u64 c) {
    u64 d;
    asm("fma.rn.f32x2 %0, %1, %2, %3;" : "=l"(d) : "l"(a), "l"(b), "l"(c));
    return d;
}

// ---------------- Pass 1: Volterra + rotation -> out ------------------------
__global__ __launch_bounds__(BLOCK)
void pa_main(const float* __restrict__ x,
             const float* __restrict__ crg,
             const float* __restrict__ cig,
             const float* __restrict__ pn,
             float* __restrict__ out)
{
    // duplicated packed coeffs: scr2[m][k] = (cr[k][m], cr[k][m])
    __shared__ u64 scr2[MEMD][4], sci2[MEMD][4];
    if (threadIdx.x < 40) {
        const int t = threadIdx.x;
        if (t < 20) {
            float v = __ldg(&crg[t]);            // t = k*5+m
            scr2[t % 5][t / 5] = pk2(v, v);
        } else {
            const int u = t - 20;
            float v = __ldg(&cig[u]);
            sci2[u % 5][u / 5] = pk2(v, v);
        }
    }
    __syncthreads();

    const int j = blockIdx.x * BLOCK + threadIdx.x;
    const int b = blockIdx.y;
    float acc = 0.f;

    if (j < JOBS_PB) {
        const float4* xb4 = (const float4*)(x + (size_t)b * SLEN * 2);
        float I[8], Q[8], a2[8];
#pragma unroll
        for (int v = 0; v < 4; v++) {
            float4 p = __ldg(&xb4[j * 2 + v]);   // samples 4j+2v, 4j+2v+1
            I[2 * v]     = p.x;  Q[2 * v]     = p.y;
            I[2 * v + 1] = p.z;  Q[2 * v + 1] = p.w;
        }
#pragma unroll
        for (int s = 0; s < 8; s++)
            a2[s] = fmaf(I[s], I[s], Q[s] * Q[s]);

        // packed adjacent-sample pairs (t, t+1)
        u64 ii[7], qq[7], mq[7], aa[7];
#pragma unroll
        for (int t = 0; t < 7; t++) {
            ii[t] = pk2(I[t], I[t + 1]);
            qq[t] = pk2(Q[t], Q[t + 1]);
            mq[t] = pk2(-Q[t], -Q[t + 1]);
            aa[t] = pk2(a2[t], a2[t + 1]);
        }

        // packed accumulators: lanes = output pair (0,1) and (2,3)
        u64 sr0 = 0, si0 = 0, sr1 = 0, si1 = 0;
#pragma unroll
        for (int m = 0; m < MEMD; m++) {
            const int t0 = 4 - m;                // windows for outputs (0,1)
            const int t1 = 6 - m;                // windows for outputs (2,3)
            u64 fr0 = fma2_(scr2[m][3], aa[t0], scr2[m][2]);
            fr0     = fma2_(fr0,        aa[t0], scr2[m][1]);
            fr0     = fma2_(fr0,        aa[t0], scr2[m][0]);
            u64 fi0 = fma2_(sci2[m][3], aa[t0], sci2[m][2]);
            fi0     = fma2_(fi0,        aa[t0], sci2[m][1]);
            fi0     = fma2_(fi0,        aa[t0], sci2[m][0]);
            sr0 = fma2_(fr0, ii[t0], sr0);
            sr0 = fma2_(fi0, mq[t0], sr0);
            si0 = fma2_(fr0, qq[t0], si0);
            si0 = fma2_(fi0, ii[t0], si0);

            u64 fr1 = fma2_(scr2[m][3], aa[t1], scr2[m][2]);
            fr1     = fma2_(fr1,        aa[t1], scr2[m][1]);
            fr1     = fma2_(fr1,        aa[t1], scr2[m][0]);
            u64 fi1 = fma2_(sci2[m][3], aa[t1], sci2[m][2]);
            fi1     = fma2_(fi1,        aa[t1], sci2[m][1]);
            fi1     = fma2_(fi1,        aa[t1], sci2[m][0]);
            sr1 = fma2_(fr1, ii[t1], sr1);
            sr1 = fma2_(fi1, mq[t1], sr1);
            si1 = fma2_(fr1, qq[t1], si1);
            si1 = fma2_(fi1, ii[t1], si1);
        }

        float yr[4], yi[4];
        upk2(sr0, yr[0], yr[1]);  upk2(si0, yi[0], yi[1]);
        upk2(sr1, yr[2], yr[3]);  upk2(si1, yi[2], yi[3]);

#pragma unroll
        for (int o = 0; o < 4; o++)
            acc = fmaf(yr[o], yr[o], fmaf(yi[o], yi[o], acc));

        // fused phase rotation (unitary; power already accumulated)
        const float4* pn4 = (const float4*)(pn + (size_t)b * OUTLEN);
        float4 p = __ldg(&pn4[j]);
        const float KRAD = 0.008726646259971648f;    // 0.5*pi/180
        float pr[4] = {p.x, p.y, p.z, p.w};
        float ov[8];
#pragma unroll
        for (int o = 0; o < 4; o++) {
            float c, s;
            __sincosf(pr[o] * KRAD, &s, &c);
            ov[2 * o]     = yr[o] * c - yi[o] * s;
            ov[2 * o + 1] = yr[o] * s + yi[o] * c;
        }
        float4* out4 = (float4*)(out + (size_t)b * OUTLEN * 2);
        out4[j * 2]     = make_float4(ov[0], ov[1], ov[2], ov[3]);
        out4[j * 2 + 1] = make_float4(ov[4], ov[5], ov[6], ov[7]);
    }

    // deterministic block reduction -> partial
    __shared__ float shr[BLOCK / 32];
#pragma unroll
    for (int off = 16; off > 0; off >>= 1)
        acc += __shfl_down_sync(0xffffffffu, acc, off);
    if ((threadIdx.x & 31) == 0) shr[threadIdx.x >> 5] = acc;
    __syncthreads();
    if (threadIdx.x < BLOCK / 32) {
        float v = shr[threadIdx.x];
#pragma unroll
        for (int off = (BLOCK / 32) / 2; off > 0; off >>= 1)
            v += __shfl_down_sync(0xffu, v, off);
        if (threadIdx.x == 0)
            g_partials[blockIdx.y * GRIDX + blockIdx.x] = v;
    }
}

// ---------------- Pass 2: noise_std (single block) ---------------------------
__global__ __launch_bounds__(256)
void pa_reduce()
{
    __shared__ double sh[256];
    double s = 0.0;
#pragma unroll
    for (int i = 0; i < NPART / 256; i++)
        s += (double)g_partials[threadIdx.x + i * 256];
    sh[threadIdx.x] = s;
    __syncthreads();
#pragma unroll
    for (int off = 128; off > 0; off >>= 1) {
        if (threadIdx.x < off) sh[threadIdx.x] += sh[threadIdx.x + off];
        __syncthreads();
    }
    if (threadIdx.x == 0) {
        double mean = sh[0] / ((double)BATCH * (double)OUTLEN);
        g_noise_std = (float)sqrt(mean * 0.5 * 1.0e-6);   // 10^(-60/10)
    }
}

// ---------------- Pass 3: out += ns * awgn ----------------------------------
__global__ __launch_bounds__(BLOCK)
void pa_epi(const float* __restrict__ awgn,
            float* __restrict__ out)
{
    const float ns = g_noise_std;
    const float4* aw4 = (const float4*)awgn;
    float4* o4 = (float4*)out;

    size_t i0 = (size_t)blockIdx.x * (2 * BLOCK) + threadIdx.x;
    // front-batch both load pairs
    float4 a0, a1, o0, o1;
    const bool v0 = i0 < EN4;
    const bool v1 = (i0 + BLOCK) < EN4;
    if (v0) { a0 = __ldg(&aw4[i0]);          o0 = o4[i0]; }
    if (v1) { a1 = __ldg(&aw4[i0 + BLOCK]);  o1 = o4[i0 + BLOCK]; }
    if (v0) {
        o0.x = fmaf(a0.x, ns, o0.x);  o0.y = fmaf(a0.y, ns, o0.y);
        o0.z = fmaf(a0.z, ns, o0.z);  o0.w = fmaf(a0.w, ns, o0.w);
        o4[i0] = o0;
    }
    if (v1) {
        o1.x = fmaf(a1.x, ns, o1.x);  o1.y = fmaf(a1.y, ns, o1.y);
        o1.z = fmaf(a1.z, ns, o1.z);  o1.w = fmaf(a1.w, ns, o1.w);
        o4[i0 + BLOCK] = o1;
    }
}

// ---------------------------------------------------------------------------
extern "C" void kernel_launch(void* const* d_in, const int* in_sizes, int n_in,
                              void* d_out, int out_size)
{
    const float* x    = (const float*)d_in[0];
    const float* cr   = (const float*)d_in[1];
    const float* ci   = (const float*)d_in[2];
    const float* awgn = (const float*)d_in[3];
    const float* pn   = (const float*)d_in[4];
    float* out        = (float*)d_out;

    pa_main<<<dim3(GRIDX, BATCH), BLOCK>>>(x, cr, ci, pn, out);
    pa_reduce<<<1, 256>>>();
    pa_epi<<<EGRID, BLOCK>>>(awgn, out);
}